// round 6
// baseline (speedup 1.0000x reference)
#include <cuda_runtime.h>
#include <math.h>
#include <stdint.h>

#define BB 512
#define SS 128
#define EE 300
#define LL 2
#define HH 300
#define FCIN 1800   // E*(1+L)*2

// ---------------- device scratch (no allocation allowed) ----------------
__device__ float g_s1[BB*SS*EE];
__device__ float g_s2[BB*SS*EE];
__device__ float g_o1[BB*SS*EE];
__device__ float g_o2[BB*SS*EE];
__device__ float g_A [BB*SS*SS];
__device__ float g_w1[BB*SS];
__device__ float g_w2[BB*SS];
__device__ float g_v1[BB*SS];
__device__ float g_v2[BB*SS];
__device__ float g_x [BB*FCIN];
__device__ float g_h [BB*HH];

__device__ __forceinline__ float tanh_fast(float x) {
    float r; asm("tanh.approx.f32 %0, %1;" : "=f"(r) : "f"(x)); return r;
}
__device__ __forceinline__ uint32_t to_tf32(float x) {
    uint32_t r; asm("cvt.rna.tf32.f32 %0, %1;" : "=r"(r) : "f"(x)); return r;
}
#define MMA_TF32(C, A, B) \
    asm volatile("mma.sync.aligned.m16n8k8.row.col.f32.tf32.tf32.f32 " \
        "{%0,%1,%2,%3}, {%4,%5,%6,%7}, {%8,%9}, {%0,%1,%2,%3};" \
        : "+f"((C)[0]), "+f"((C)[1]), "+f"((C)[2]), "+f"((C)[3]) \
        : "r"((A)[0]), "r"((A)[1]), "r"((A)[2]), "r"((A)[3]), \
          "r"((B)[0]), "r"((B)[1]))

// ---------------- embedding gather + masks + fused mean(slot0) ----------------
__global__ __launch_bounds__(256) void k_gather(const int* __restrict__ seq1,
                                                const int* __restrict__ seq2,
                                                const float* __restrict__ emb) {
    __shared__ float msum[2][EE];
    int b = blockIdx.x;
    int tid = threadIdx.x;
    int warp = tid >> 5, lane = tid & 31;
    for (int i = tid; i < 2*EE; i += 256) ((float*)msum)[i] = 0.f;
    for (int i = tid; i < SS; i += 256) {
        g_v1[b*SS+i] = (seq1[b*SS+i] != 0) ? 1.f : 0.f;
        g_v2[b*SS+i] = (seq2[b*SS+i] != 0) ? 1.f : 0.f;
    }
    __syncthreads();
    for (int idx = warp; idx < 2*SS; idx += 8) {
        int s = idx >> 1, sel = idx & 1;
        int tok = sel ? seq2[b*SS+s] : seq1[b*SS+s];
        const float4* src = (const float4*)(emb + (long)tok*EE);
        float4* dst = (float4*)((sel ? g_s2 : g_s1) + (b*SS+s)*EE);
        for (int j = lane; j < EE/4; j += 32) {
            float4 v = src[j];
            dst[j] = v;
            atomicAdd(&msum[sel][4*j+0], v.x);
            atomicAdd(&msum[sel][4*j+1], v.y);
            atomicAdd(&msum[sel][4*j+2], v.z);
            atomicAdd(&msum[sel][4*j+3], v.w);
        }
    }
    __syncthreads();
    for (int e = tid; e < EE; e += 256) {
        g_x[b*FCIN + e]        = msum[0][e]*(1.f/SS);
        g_x[b*FCIN + 3*EE + e] = msum[1][e]*(1.f/SS);
    }
}

// ---------------- match-score, tensor-core tf32 ----------------
// mode=0: s1/s2 -> store A     mode=1: o1/o2 -> w1 (row sums), w2 (col sums)
#define MPAD 36
#define MCH 10      // ceil(300/32)
__global__ __launch_bounds__(256) void k_match(int mode) {
    extern __shared__ float sm[];
    float* Xs = sm;                       // [2][128][36]
    float* Ys = Xs + 2*SS*MPAD;           // [2][128][36]
    float* n1s = Ys + 2*SS*MPAD;          // [128]
    float* n2s = n1s + SS;                // [128]
    float* rowbuf = n2s + SS;             // [4][128]
    float* colbuf = rowbuf + 4*SS;        // [2][128]

    int b = blockIdx.x;
    const float* X = (mode ? g_o1 : g_s1) + b*SS*EE;
    const float* Y = (mode ? g_o2 : g_s2) + b*SS*EE;
    int tid = threadIdx.x;
    int lane = tid & 31, wid = tid >> 5;
    int g = lane >> 2, tig = lane & 3;
    int wm = wid & 1, wn = wid >> 1;

    int lr = tid >> 1, lh = tid & 1;
    const float* Xr = X + lr*EE + lh*16;
    const float* Yr = Y + lr*EE + lh*16;
    float mvx = g_v1[b*SS + lr];
    float mvy = g_v2[b*SS + lr];
    float nx = 0.f, ny = 0.f;
    float4 vx[4], vy[4];

#define FETCH(c) do { \
    int kb = (c)*32; \
    _Pragma("unroll") for (int j = 0; j < 4; j++) { \
        int k = kb + lh*16 + 4*j; \
        if (k < EE) { vx[j] = *(const float4*)(Xr + kb + 4*j); \
                      vy[j] = *(const float4*)(Yr + kb + 4*j); } \
        else { vx[j] = make_float4(0.f,0.f,0.f,0.f); vy[j] = vx[j]; } \
    } } while(0)

#define STBUF(buf) do { \
    float* xd = Xs + (buf)*SS*MPAD + lr*MPAD + lh*16; \
    float* yd = Ys + (buf)*SS*MPAD + lr*MPAD + lh*16; \
    _Pragma("unroll") for (int j = 0; j < 4; j++) { \
        float x0=vx[j].x*mvx, x1=vx[j].y*mvx, x2=vx[j].z*mvx, x3=vx[j].w*mvx; \
        float y0=vy[j].x*mvy, y1=vy[j].y*mvy, y2=vy[j].z*mvy, y3=vy[j].w*mvy; \
        nx += x0*x0+x1*x1+x2*x2+x3*x3; \
        ny += y0*y0+y1*y1+y2*y2+y3*y3; \
        ((uint32_t*)xd)[4*j+0]=to_tf32(x0); ((uint32_t*)xd)[4*j+1]=to_tf32(x1); \
        ((uint32_t*)xd)[4*j+2]=to_tf32(x2); ((uint32_t*)xd)[4*j+3]=to_tf32(x3); \
        ((uint32_t*)yd)[4*j+0]=to_tf32(y0); ((uint32_t*)yd)[4*j+1]=to_tf32(y1); \
        ((uint32_t*)yd)[4*j+2]=to_tf32(y2); ((uint32_t*)yd)[4*j+3]=to_tf32(y3); \
    } } while(0)

    float acc[4][4][4];
#pragma unroll
    for (int mt = 0; mt < 4; mt++)
#pragma unroll
        for (int nt = 0; nt < 4; nt++)
#pragma unroll
            for (int q = 0; q < 4; q++) acc[mt][nt][q] = 0.f;

    FETCH(0); STBUF(0);
    __syncthreads();

    for (int c = 0; c < MCH; c++) {
        int cur = c & 1;
        if (c + 1 < MCH) FETCH(c+1);
        const uint32_t* xb = (const uint32_t*)(Xs + cur*SS*MPAD);
        const uint32_t* yb = (const uint32_t*)(Ys + cur*SS*MPAD);
#pragma unroll
        for (int ks = 0; ks < 4; ks++) {
            int kk = ks*8;
            uint32_t a[4][4], bf[4][2];
#pragma unroll
            for (int mt = 0; mt < 4; mt++) {
                int row = wm*64 + mt*16 + g;
                a[mt][0] = xb[row*MPAD + kk + tig];
                a[mt][1] = xb[(row+8)*MPAD + kk + tig];
                a[mt][2] = xb[row*MPAD + kk + tig + 4];
                a[mt][3] = xb[(row+8)*MPAD + kk + tig + 4];
            }
#pragma unroll
            for (int nt = 0; nt < 4; nt++) {
                int cr = wn*32 + nt*8 + g;
                bf[nt][0] = yb[cr*MPAD + kk + tig];
                bf[nt][1] = yb[cr*MPAD + kk + tig + 4];
            }
#pragma unroll
            for (int mt = 0; mt < 4; mt++)
#pragma unroll
                for (int nt = 0; nt < 4; nt++)
                    MMA_TF32(acc[mt][nt], a[mt], bf[nt]);
        }
        if (c + 1 < MCH) STBUF(cur ^ 1);
        __syncthreads();
    }

    nx += __shfl_xor_sync(0xffffffffu, nx, 1);
    ny += __shfl_xor_sync(0xffffffffu, ny, 1);
    if (lh == 0) { n1s[lr] = nx; n2s[lr] = ny; }
    __syncthreads();

    if (mode == 0) {
        float* Ao = g_A + b*SS*SS;
#pragma unroll
        for (int mt = 0; mt < 4; mt++) {
            int row = wm*64 + mt*16 + g;
            float nr0 = n1s[row], nr1 = n1s[row+8];
#pragma unroll
            for (int nt = 0; nt < 4; nt++) {
                int col = wn*32 + nt*8 + 2*tig;
                float nc0 = n2s[col], nc1 = n2s[col+1];
                float d00 = sqrtf(fmaxf(nr0 + nc0 - 2.f*acc[mt][nt][0], 0.f));
                float d01 = sqrtf(fmaxf(nr0 + nc1 - 2.f*acc[mt][nt][1], 0.f));
                float d10 = sqrtf(fmaxf(nr1 + nc0 - 2.f*acc[mt][nt][2], 0.f));
                float d11 = sqrtf(fmaxf(nr1 + nc1 - 2.f*acc[mt][nt][3], 0.f));
                *(float2*)(Ao + row*SS + col)     = make_float2(1.f/(1.f+d00), 1.f/(1.f+d01));
                *(float2*)(Ao + (row+8)*SS + col) = make_float2(1.f/(1.f+d10), 1.f/(1.f+d11));
            }
        }
    } else {
        float cs0[4], cs1[4];
#pragma unroll
        for (int nt = 0; nt < 4; nt++) { cs0[nt] = 0.f; cs1[nt] = 0.f; }
#pragma unroll
        for (int mt = 0; mt < 4; mt++) {
            int row = wm*64 + mt*16 + g;
            float nr0 = n1s[row], nr1 = n1s[row+8];
            float rlo = 0.f, rhi = 0.f;
#pragma unroll
            for (int nt = 0; nt < 4; nt++) {
                int col = wn*32 + nt*8 + 2*tig;
                float nc0 = n2s[col], nc1 = n2s[col+1];
                float a00 = 1.f/(1.f + sqrtf(fmaxf(nr0 + nc0 - 2.f*acc[mt][nt][0], 0.f)));
                float a01 = 1.f/(1.f + sqrtf(fmaxf(nr0 + nc1 - 2.f*acc[mt][nt][1], 0.f)));
                float a10 = 1.f/(1.f + sqrtf(fmaxf(nr1 + nc0 - 2.f*acc[mt][nt][2], 0.f)));
                float a11 = 1.f/(1.f + sqrtf(fmaxf(nr1 + nc1 - 2.f*acc[mt][nt][3], 0.f)));
                rlo += a00 + a01;
                rhi += a10 + a11;
                cs0[nt] += a00 + a10;
                cs1[nt] += a01 + a11;
            }
            rlo += __shfl_xor_sync(0xffffffffu, rlo, 1);
            rlo += __shfl_xor_sync(0xffffffffu, rlo, 2);
            rhi += __shfl_xor_sync(0xffffffffu, rhi, 1);
            rhi += __shfl_xor_sync(0xffffffffu, rhi, 2);
            if (tig == 0) {
                rowbuf[wn*SS + row]   = rlo;
                rowbuf[wn*SS + row+8] = rhi;
            }
        }
#pragma unroll
        for (int nt = 0; nt < 4; nt++) {
            float c0 = cs0[nt], c1 = cs1[nt];
            c0 += __shfl_xor_sync(0xffffffffu, c0, 4);
            c0 += __shfl_xor_sync(0xffffffffu, c0, 8);
            c0 += __shfl_xor_sync(0xffffffffu, c0, 16);
            c1 += __shfl_xor_sync(0xffffffffu, c1, 4);
            c1 += __shfl_xor_sync(0xffffffffu, c1, 8);
            c1 += __shfl_xor_sync(0xffffffffu, c1, 16);
            if (g == 0) {
                int col = wn*32 + nt*8 + 2*tig;
                colbuf[wm*SS + col]     = c0;
                colbuf[wm*SS + col + 1] = c1;
            }
        }
        __syncthreads();
        if (tid < SS) {
            g_w1[b*SS + tid] = rowbuf[tid] + rowbuf[SS+tid] + rowbuf[2*SS+tid] + rowbuf[3*SS+tid];
            g_w2[b*SS + tid] = colbuf[tid] + colbuf[SS+tid];
        }
    }
#undef FETCH
#undef STBUF
}

// ---------------- fused fgemm + conv + mean, SPLIT PER PAIR: grid (B,5,2) ------
// pair=0: f1 = A@W, conv(s1,f1)->o1 ; pair=1: f2 = A^T@W, conv(s2,f2)->o2
// output cols [60y, 60y+60); f computed for cols [60y-2, 60y+62)
#define FPAD 132
// smem layout (words): phase1 As[128][132]@0 (16896), Ws[64][132]@16896 (8448)
//                      phase2 fs[128][67]@0 (8576), ss[128][65]@8576 (8320),
//                             os[128][61]@16896 (7808)
// wv[18] @ 25344 (beyond both phases)
#define FGC_WORDS (16896 + 8448 + 32)
__global__ __launch_bounds__(256) void k_fgc(const float* __restrict__ W,
                                             const float* __restrict__ cw,
                                             const float* __restrict__ cb, int layer) {
    extern __shared__ float sm[];
    uint32_t* As = (uint32_t*)sm;
    uint32_t* Ws = (uint32_t*)(sm + 16896);
    float* fs = sm;
    float* ss = sm + 8576;
    float* os = sm + 16896;
    float* wv = sm + 25344;

    int b = blockIdx.x, y = blockIdx.y, pair = blockIdx.z;
    int nb = 60*y - 2;
    const float* Ab = g_A + b*SS*SS;
    const float* Wl = W + (size_t)layer*SS*EE;
    int tid = threadIdx.x;
    int lane = tid & 31, wid = tid >> 5;
    int g = lane >> 2, tig = lane & 3;

    if (tid < 18) wv[tid] = cw[layer*18 + tid];

    // load A (128x128) -> tf32 smem (row-major; pair=1 reads it transposed)
    {
        int r = tid >> 1, h = tid & 1;
        const float* src = Ab + r*SS + h*64;
        uint32_t* dst = As + r*FPAD + h*64;
#pragma unroll
        for (int q = 0; q < 16; q++) {
            float4 v = *(const float4*)(src + 4*q);
            dst[4*q+0] = to_tf32(v.x); dst[4*q+1] = to_tf32(v.y);
            dst[4*q+2] = to_tf32(v.z); dst[4*q+3] = to_tf32(v.w);
        }
    }
    // load W tile transposed with edge guards: Ws[n][k], n in [nb, nb+64)
    {
        int k = tid >> 1, h = tid & 1;
#pragma unroll
        for (int q = 0; q < 8; q++) {
            int nl = h*32 + 4*q;
#pragma unroll
            for (int t = 0; t < 4; t++) {
                int n = nb + nl + t;
                float v = (n >= 0 && n < EE) ? Wl[k*EE + n] : 0.f;
                Ws[(nl+t)*FPAD + k] = to_tf32(v);
            }
        }
    }
    __syncthreads();

    // GEMM: 8 warps, warp wid -> rows [wid*16, wid*16+16), all 64 cols
    float acc[8][4];
#pragma unroll
    for (int nt = 0; nt < 8; nt++)
#pragma unroll
        for (int q = 0; q < 4; q++) acc[nt][q] = 0.f;

    int row = wid*16 + g;
#pragma unroll 4
    for (int ks = 0; ks < 16; ks++) {
        int kk = ks*8;
        uint32_t a[4], bf[8][2];
        if (pair == 0) {
            a[0] = As[row*FPAD + kk + tig];
            a[1] = As[(row+8)*FPAD + kk + tig];
            a[2] = As[row*FPAD + kk + tig + 4];
            a[3] = As[(row+8)*FPAD + kk + tig + 4];
        } else {
            a[0] = As[(kk+tig)*FPAD + row];
            a[1] = As[(kk+tig)*FPAD + row + 8];
            a[2] = As[(kk+tig+4)*FPAD + row];
            a[3] = As[(kk+tig+4)*FPAD + row + 8];
        }
#pragma unroll
        for (int nt = 0; nt < 8; nt++) {
            int cn = nt*8 + g;
            bf[nt][0] = Ws[cn*FPAD + kk + tig];
            bf[nt][1] = Ws[cn*FPAD + kk + tig + 4];
        }
#pragma unroll
        for (int nt = 0; nt < 8; nt++)
            MMA_TF32(acc[nt], a, bf[nt]);
    }
    __syncthreads();   // phase1 regions dead

    // store f (registers -> smem [128][67])
#pragma unroll
    for (int nt = 0; nt < 8; nt++) {
        int col = nt*8 + 2*tig;
        fs[row*67 + col]       = acc[nt][0];
        fs[row*67 + col + 1]   = acc[nt][1];
        fs[(row+8)*67 + col]     = acc[nt][2];
        fs[(row+8)*67 + col + 1] = acc[nt][3];
    }
    // load s tile: 128 rows x 62 cols (global cols [60y-1, 60y+61))
    {
        const float* Sx = (pair ? g_s2 : g_s1) + b*SS*EE;
        for (int i = tid; i < 128*62; i += 256) {
            int r = i / 62, c = i % 62;
            int n = nb + 1 + c;
            ss[r*65 + c] = (n >= 0 && n < EE) ? Sx[r*EE + n] : 0.f;
        }
    }
    __syncthreads();

    // conv: 2 threads per row, each 30 output cols, rolling window
    {
        int r = tid >> 1, seg = tid & 1;
        int e0 = seg*30;
        const float* sb = ss + r*65;
        const float* fb = fs + r*67;
        float* ob = os + r*61;
        bool rm = r > 0, rp = r < 127;
        const float* sm1 = sb - 65; const float* sp1 = sb + 65;
        const float* fm1 = fb - 67; const float* fp1 = fb + 67;
        float bias = cb[layer];
        float sv[3][3], fv[3][3];
        sv[0][0] = rm ? sm1[e0] : 0.f;   sv[0][1] = rm ? sm1[e0+1] : 0.f;
        sv[1][0] = sb[e0];               sv[1][1] = sb[e0+1];
        sv[2][0] = rp ? sp1[e0] : 0.f;   sv[2][1] = rp ? sp1[e0+1] : 0.f;
        fv[0][0] = rm ? fm1[e0+1] : 0.f; fv[0][1] = rm ? fm1[e0+2] : 0.f;
        fv[1][0] = fb[e0+1];             fv[1][1] = fb[e0+2];
        fv[2][0] = rp ? fp1[e0+1] : 0.f; fv[2][1] = rp ? fp1[e0+2] : 0.f;
        for (int e = e0; e < e0+30; e++) {
            sv[0][2] = rm ? sm1[e+2] : 0.f;
            sv[1][2] = sb[e+2];
            sv[2][2] = rp ? sp1[e+2] : 0.f;
            fv[0][2] = rm ? fm1[e+3] : 0.f;
            fv[1][2] = fb[e+3];
            fv[2][2] = rp ? fp1[e+3] : 0.f;
            float a2 = bias;
#pragma unroll
            for (int kh = 0; kh < 3; kh++)
#pragma unroll
                for (int kw = 0; kw < 3; kw++)
                    a2 += wv[kh*3+kw]*sv[kh][kw] + wv[9+kh*3+kw]*fv[kh][kw];
            ob[e] = tanh_fast(a2);
#pragma unroll
            for (int kh = 0; kh < 3; kh++) {
                sv[kh][0] = sv[kh][1]; sv[kh][1] = sv[kh][2];
                fv[kh][0] = fv[kh][1]; fv[kh][1] = fv[kh][2];
            }
        }
    }
    __syncthreads();

    // coalesced o write-out
    {
        float* O = (pair ? g_o2 : g_o1) + b*SS*EE;
        for (int i = tid; i < 128*60; i += 256) {
            int r = i / 60, e = i % 60;
            O[r*EE + 60*y + e] = os[r*61 + e];
        }
    }
    // column means -> g_x (each col owned by exactly one CTA)
    if (tid < 60) {
        float s = 0.f;
#pragma unroll 8
        for (int r = 0; r < 128; r++) s += os[r*61 + tid];
        int slot = (pair ? 4 : 1) + layer;
        g_x[b*FCIN + slot*EE + 60*y + tid] = s*(1.f/SS);
    }
}

// ---------------- weighted avg-pool3 + residual update ----------------
#define CROWS 16
__global__ __launch_bounds__(128) void k_pool() {
    int b = blockIdx.x, ch = blockIdx.y, pair = blockIdx.z;
    int s0 = ch * CROWS;
    const float* O = (pair ? g_o2 : g_o1) + b*SS*EE;
    float* Sx = (pair ? g_s2 : g_s1) + b*SS*EE;
    const float* wv = (pair ? g_w2 : g_w1) + b*SS;
    __shared__ float w[CROWS+2];
    if (threadIdx.x < CROWS+2) {
        int s = s0 + (int)threadIdx.x - 1;
        w[threadIdx.x] = (s >= 0 && s < SS) ? wv[s] : 0.f;
    }
    __syncthreads();
    for (int e = threadIdx.x; e < EE; e += 128) {
        float a = (s0 > 0) ? O[(s0-1)*EE + e] * w[0] : 0.f;
        float bmid = O[s0*EE + e] * w[1];
#pragma unroll
        for (int i = 0; i < CROWS; i++) {
            int s = s0 + i;
            float cnext = (s+1 < SS) ? O[(s+1)*EE + e] * w[i+2] : 0.f;
            Sx[s*EE + e] += (a + bmid + cnext) * (1.f/3.f);
            a = bmid; bmid = cnext;
        }
    }
}

// ---------------- fc1 GEMM: [512,1800] @ [1800,300]^T -> g_h ----------------
__global__ __launch_bounds__(256) void k_fc1(const float* __restrict__ fw) {
    int m0 = blockIdx.x * 64, n0 = blockIdx.y * 64;
    __shared__ float Xs[8][68];
    __shared__ float Ws2[8][68];
    int tid = threadIdx.x, ty = tid >> 4, tx = tid & 15;
    float acc[4][4];
#pragma unroll
    for (int u = 0; u < 4; u++)
#pragma unroll
        for (int v = 0; v < 4; v++) acc[u][v] = 0.f;

    for (int k0 = 0; k0 < FCIN; k0 += 8) {
        __syncthreads();
#pragma unroll 2
        for (int i = tid; i < 512; i += 256) {
            int r = i >> 3, kk = i & 7;
            Xs[kk][r] = g_x[(m0 + r)*FCIN + k0 + kk];
            int n = n0 + r;
            Ws2[kk][r] = (n < HH) ? fw[n*FCIN + k0 + kk] : 0.f;
        }
        __syncthreads();
#pragma unroll
        for (int kk = 0; kk < 8; kk++) {
            float4 xa = *(const float4*)&Xs[kk][ty*4];
            float4 wb = *(const float4*)&Ws2[kk][tx*4];
            float xv[4] = {xa.x, xa.y, xa.z, xa.w};
            float wvv[4] = {wb.x, wb.y, wb.z, wb.w};
#pragma unroll
            for (int u = 0; u < 4; u++)
#pragma unroll
                for (int v = 0; v < 4; v++) acc[u][v] += xv[u]*wvv[v];
        }
    }
#pragma unroll
    for (int u = 0; u < 4; u++) {
        int m = m0 + ty*4 + u;
#pragma unroll
        for (int v = 0; v < 4; v++) {
            int n = n0 + tx*4 + v;
            if (n < HH) g_h[m*HH + n] = acc[u][v];
        }
    }
}

// ---------------- LN + relu + fc2 + softmax ----------------
__device__ __forceinline__ float block_reduce512(float v, float* red) {
    int tid = threadIdx.x;
    red[tid] = v;
    __syncthreads();
    for (int off = 256; off > 0; off >>= 1) {
        if (tid < off) red[tid] += red[tid + off];
        __syncthreads();
    }
    float r = red[0];
    __syncthreads();
    return r;
}

__global__ __launch_bounds__(512) void k_head(const float* __restrict__ fc1b,
                                              const float* __restrict__ lng,
                                              const float* __restrict__ lnb,
                                              const float* __restrict__ fc2w,
                                              const float* __restrict__ fc2b,
                                              float* __restrict__ out) {
    int b = blockIdx.x, tid = threadIdx.x;
    __shared__ float red[512];
    bool act = tid < HH;
    float h = act ? (g_h[b*HH + tid] + fc1b[tid]) : 0.f;
    float mu = block_reduce512(h, red) * (1.f/HH);
    float d = act ? (h - mu) : 0.f;
    float var = block_reduce512(d*d, red) * (1.f/HH);
    float hn = 0.f;
    if (act) {
        hn = d * rsqrtf(var + 1e-5f) * lng[tid] + lnb[tid];
        hn = fmaxf(hn, 0.f);
    }
    float o0 = block_reduce512(act ? hn*fc2w[tid]      : 0.f, red);
    float o1 = block_reduce512(act ? hn*fc2w[HH + tid] : 0.f, red);
    if (tid == 0) {
        o0 += fc2b[0];
        o1 += fc2b[1];
        out[b*2 + 0] = o0;
        out[b*2 + 1] = o1;
        float m = fmaxf(o0, o1);
        float e0 = expf(o0 - m), e1 = expf(o1 - m);
        float inv = 1.f/(e0 + e1);
        out[BB*2 + b*2 + 0] = e0*inv;
        out[BB*2 + b*2 + 1] = e1*inv;
    }
}

// ---------------- launch ----------------
extern "C" void kernel_launch(void* const* d_in, const int* in_sizes, int n_in,
                              void* d_out, int out_size) {
    (void)in_sizes; (void)n_in; (void)out_size;
    const int*   seq1 = (const int*)d_in[0];
    const int*   seq2 = (const int*)d_in[1];
    const float* emb  = (const float*)d_in[2];
    const float* W    = (const float*)d_in[3];
    const float* cw   = (const float*)d_in[4];
    const float* cb   = (const float*)d_in[5];
    const float* fc1w = (const float*)d_in[6];
    const float* fc1b = (const float*)d_in[7];
    const float* lng  = (const float*)d_in[8];
    const float* lnb  = (const float*)d_in[9];
    const float* fc2w = (const float*)d_in[10];
    const float* fc2b = (const float*)d_in[11];
    float* out = (float*)d_out;

    const int SM_MATCH = (2*SS*MPAD*2 + 2*SS + 4*SS + 2*SS) * 4;   // ~77.8KB
    const int SM_FG    = FGC_WORDS * 4;                             // ~101.5KB

    cudaFuncSetAttribute(k_match, cudaFuncAttributeMaxDynamicSharedMemorySize, SM_MATCH);
    cudaFuncSetAttribute(k_fgc,   cudaFuncAttributeMaxDynamicSharedMemorySize, SM_FG);

    k_gather<<<BB, 256>>>(seq1, seq2, emb);
    for (int l = 0; l < LL; l++) {
        k_match<<<BB, 256, SM_MATCH>>>(0);
        k_fgc<<<dim3(BB, 5, 2), 256, SM_FG>>>(W, cw, cb, l);
        k_match<<<BB, 256, SM_MATCH>>>(1);
        k_pool<<<dim3(BB, 8, 2), 128>>>();
    }
    k_fc1<<<dim3(8, 5), 256>>>(fc1w);
    k_head<<<BB, 512>>>(fc1b, lng, lnb, fc2w, fc2b, out);
}

// round 7
// speedup vs baseline: 1.4099x; 1.4099x over previous
#include <cuda_runtime.h>
#include <math.h>
#include <stdint.h>

#define BB 512
#define SS 128
#define EE 300
#define LL 2
#define HH 300
#define FCIN 1800   // E*(1+L)*2
#define CROWS 16

// ---------------- device scratch (no allocation allowed) ----------------
__device__ float g_s1[BB*SS*EE];
__device__ float g_s2[BB*SS*EE];
__device__ float g_f1[BB*SS*EE];
__device__ float g_f2[BB*SS*EE];
__device__ float g_o1[BB*SS*EE];
__device__ float g_o2[BB*SS*EE];
__device__ float g_A [BB*SS*SS];
__device__ float g_w1[BB*SS];
__device__ float g_w2[BB*SS];
__device__ float g_v1[BB*SS];
__device__ float g_v2[BB*SS];
__device__ float g_x [BB*FCIN];
__device__ float g_h [BB*HH];

__device__ __forceinline__ float tanh_fast(float x) {
    float r; asm("tanh.approx.f32 %0, %1;" : "=f"(r) : "f"(x)); return r;
}
__device__ __forceinline__ uint32_t to_tf32(float x) {
    uint32_t r; asm("cvt.rna.tf32.f32 %0, %1;" : "=r"(r) : "f"(x)); return r;
}
#define MMA_TF32(C, A, B) \
    asm volatile("mma.sync.aligned.m16n8k8.row.col.f32.tf32.tf32.f32 " \
        "{%0,%1,%2,%3}, {%4,%5,%6,%7}, {%8,%9}, {%0,%1,%2,%3};" \
        : "+f"((C)[0]), "+f"((C)[1]), "+f"((C)[2]), "+f"((C)[3]) \
        : "r"((A)[0]), "r"((A)[1]), "r"((A)[2]), "r"((A)[3]), \
          "r"((B)[0]), "r"((B)[1]))

// ---------------- embedding gather + masks + fused mean(slot0) ----------------
__global__ __launch_bounds__(256) void k_gather(const int* __restrict__ seq1,
                                                const int* __restrict__ seq2,
                                                const float* __restrict__ emb) {
    __shared__ float msum[2][EE];
    int b = blockIdx.x;
    int tid = threadIdx.x;
    int warp = tid >> 5, lane = tid & 31;
    for (int i = tid; i < 2*EE; i += 256) ((float*)msum)[i] = 0.f;
    for (int i = tid; i < SS; i += 256) {
        g_v1[b*SS+i] = (seq1[b*SS+i] != 0) ? 1.f : 0.f;
        g_v2[b*SS+i] = (seq2[b*SS+i] != 0) ? 1.f : 0.f;
    }
    __syncthreads();
    for (int idx = warp; idx < 2*SS; idx += 8) {
        int s = idx >> 1, sel = idx & 1;
        int tok = sel ? seq2[b*SS+s] : seq1[b*SS+s];
        const float4* src = (const float4*)(emb + (long)tok*EE);
        float4* dst = (float4*)((sel ? g_s2 : g_s1) + (b*SS+s)*EE);
        for (int j = lane; j < EE/4; j += 32) {
            float4 v = src[j];
            dst[j] = v;
            atomicAdd(&msum[sel][4*j+0], v.x);
            atomicAdd(&msum[sel][4*j+1], v.y);
            atomicAdd(&msum[sel][4*j+2], v.z);
            atomicAdd(&msum[sel][4*j+3], v.w);
        }
    }
    __syncthreads();
    for (int e = tid; e < EE; e += 256) {
        g_x[b*FCIN + e]        = msum[0][e]*(1.f/SS);
        g_x[b*FCIN + 3*EE + e] = msum[1][e]*(1.f/SS);
    }
}

// ---------------- zero mean slots for layer l (conv accumulates atomically) ----
__global__ void k_zx(int l) {
    int i = blockIdx.x*256 + threadIdx.x;
    if (i >= BB*2*EE) return;
    int b = i / (2*EE);
    int r = i % (2*EE);
    int half = r / EE, e = r % EE;
    int slot = half ? (4+l) : (1+l);
    g_x[b*FCIN + slot*EE + e] = 0.f;
}

// ---------------- match-score, tensor-core tf32 ----------------
// mode=0: s1/s2 -> store A     mode=1: o1/o2 -> w1 (row sums), w2 (col sums)
#define MPAD 36
#define MCH 10      // ceil(300/32)
__global__ __launch_bounds__(256) void k_match(int mode) {
    extern __shared__ float sm[];
    float* Xs = sm;                       // [2][128][36]
    float* Ys = Xs + 2*SS*MPAD;           // [2][128][36]
    float* n1s = Ys + 2*SS*MPAD;          // [128]
    float* n2s = n1s + SS;                // [128]
    float* rowbuf = n2s + SS;             // [4][128]
    float* colbuf = rowbuf + 4*SS;        // [2][128]

    int b = blockIdx.x;
    const float* X = (mode ? g_o1 : g_s1) + b*SS*EE;
    const float* Y = (mode ? g_o2 : g_s2) + b*SS*EE;
    int tid = threadIdx.x;
    int lane = tid & 31, wid = tid >> 5;
    int g = lane >> 2, tig = lane & 3;
    int wm = wid & 1, wn = wid >> 1;

    int lr = tid >> 1, lh = tid & 1;
    const float* Xr = X + lr*EE + lh*16;
    const float* Yr = Y + lr*EE + lh*16;
    float mvx = g_v1[b*SS + lr];
    float mvy = g_v2[b*SS + lr];
    float nx = 0.f, ny = 0.f;
    float4 vx[4], vy[4];

#define FETCH(c) do { \
    int kb = (c)*32; \
    _Pragma("unroll") for (int j = 0; j < 4; j++) { \
        int k = kb + lh*16 + 4*j; \
        if (k < EE) { vx[j] = *(const float4*)(Xr + kb + 4*j); \
                      vy[j] = *(const float4*)(Yr + kb + 4*j); } \
        else { vx[j] = make_float4(0.f,0.f,0.f,0.f); vy[j] = vx[j]; } \
    } } while(0)

#define STBUF(buf) do { \
    float* xd = Xs + (buf)*SS*MPAD + lr*MPAD + lh*16; \
    float* yd = Ys + (buf)*SS*MPAD + lr*MPAD + lh*16; \
    _Pragma("unroll") for (int j = 0; j < 4; j++) { \
        float x0=vx[j].x*mvx, x1=vx[j].y*mvx, x2=vx[j].z*mvx, x3=vx[j].w*mvx; \
        float y0=vy[j].x*mvy, y1=vy[j].y*mvy, y2=vy[j].z*mvy, y3=vy[j].w*mvy; \
        nx += x0*x0+x1*x1+x2*x2+x3*x3; \
        ny += y0*y0+y1*y1+y2*y2+y3*y3; \
        ((uint32_t*)xd)[4*j+0]=to_tf32(x0); ((uint32_t*)xd)[4*j+1]=to_tf32(x1); \
        ((uint32_t*)xd)[4*j+2]=to_tf32(x2); ((uint32_t*)xd)[4*j+3]=to_tf32(x3); \
        ((uint32_t*)yd)[4*j+0]=to_tf32(y0); ((uint32_t*)yd)[4*j+1]=to_tf32(y1); \
        ((uint32_t*)yd)[4*j+2]=to_tf32(y2); ((uint32_t*)yd)[4*j+3]=to_tf32(y3); \
    } } while(0)

    float acc[4][4][4];
#pragma unroll
    for (int mt = 0; mt < 4; mt++)
#pragma unroll
        for (int nt = 0; nt < 4; nt++)
#pragma unroll
            for (int q = 0; q < 4; q++) acc[mt][nt][q] = 0.f;

    FETCH(0); STBUF(0);
    __syncthreads();

    for (int c = 0; c < MCH; c++) {
        int cur = c & 1;
        if (c + 1 < MCH) FETCH(c+1);
        const uint32_t* xb = (const uint32_t*)(Xs + cur*SS*MPAD);
        const uint32_t* yb = (const uint32_t*)(Ys + cur*SS*MPAD);
#pragma unroll
        for (int ks = 0; ks < 4; ks++) {
            int kk = ks*8;
            uint32_t a[4][4], bf[4][2];
#pragma unroll
            for (int mt = 0; mt < 4; mt++) {
                int row = wm*64 + mt*16 + g;
                a[mt][0] = xb[row*MPAD + kk + tig];
                a[mt][1] = xb[(row+8)*MPAD + kk + tig];
                a[mt][2] = xb[row*MPAD + kk + tig + 4];
                a[mt][3] = xb[(row+8)*MPAD + kk + tig + 4];
            }
#pragma unroll
            for (int nt = 0; nt < 4; nt++) {
                int cr = wn*32 + nt*8 + g;
                bf[nt][0] = yb[cr*MPAD + kk + tig];
                bf[nt][1] = yb[cr*MPAD + kk + tig + 4];
            }
#pragma unroll
            for (int mt = 0; mt < 4; mt++)
#pragma unroll
                for (int nt = 0; nt < 4; nt++)
                    MMA_TF32(acc[mt][nt], a[mt], bf[nt]);
        }
        if (c + 1 < MCH) STBUF(cur ^ 1);
        __syncthreads();
    }

    nx += __shfl_xor_sync(0xffffffffu, nx, 1);
    ny += __shfl_xor_sync(0xffffffffu, ny, 1);
    if (lh == 0) { n1s[lr] = nx; n2s[lr] = ny; }
    __syncthreads();

    if (mode == 0) {
        float* Ao = g_A + b*SS*SS;
#pragma unroll
        for (int mt = 0; mt < 4; mt++) {
            int row = wm*64 + mt*16 + g;
            float nr0 = n1s[row], nr1 = n1s[row+8];
#pragma unroll
            for (int nt = 0; nt < 4; nt++) {
                int col = wn*32 + nt*8 + 2*tig;
                float nc0 = n2s[col], nc1 = n2s[col+1];
                float d00 = sqrtf(fmaxf(nr0 + nc0 - 2.f*acc[mt][nt][0], 0.f));
                float d01 = sqrtf(fmaxf(nr0 + nc1 - 2.f*acc[mt][nt][1], 0.f));
                float d10 = sqrtf(fmaxf(nr1 + nc0 - 2.f*acc[mt][nt][2], 0.f));
                float d11 = sqrtf(fmaxf(nr1 + nc1 - 2.f*acc[mt][nt][3], 0.f));
                *(float2*)(Ao + row*SS + col)     = make_float2(1.f/(1.f+d00), 1.f/(1.f+d01));
                *(float2*)(Ao + (row+8)*SS + col) = make_float2(1.f/(1.f+d10), 1.f/(1.f+d11));
            }
        }
    } else {
        float cs0[4], cs1[4];
#pragma unroll
        for (int nt = 0; nt < 4; nt++) { cs0[nt] = 0.f; cs1[nt] = 0.f; }
#pragma unroll
        for (int mt = 0; mt < 4; mt++) {
            int row = wm*64 + mt*16 + g;
            float nr0 = n1s[row], nr1 = n1s[row+8];
            float rlo = 0.f, rhi = 0.f;
#pragma unroll
            for (int nt = 0; nt < 4; nt++) {
                int col = wn*32 + nt*8 + 2*tig;
                float nc0 = n2s[col], nc1 = n2s[col+1];
                float a00 = 1.f/(1.f + sqrtf(fmaxf(nr0 + nc0 - 2.f*acc[mt][nt][0], 0.f)));
                float a01 = 1.f/(1.f + sqrtf(fmaxf(nr0 + nc1 - 2.f*acc[mt][nt][1], 0.f)));
                float a10 = 1.f/(1.f + sqrtf(fmaxf(nr1 + nc0 - 2.f*acc[mt][nt][2], 0.f)));
                float a11 = 1.f/(1.f + sqrtf(fmaxf(nr1 + nc1 - 2.f*acc[mt][nt][3], 0.f)));
                rlo += a00 + a01;
                rhi += a10 + a11;
                cs0[nt] += a00 + a10;
                cs1[nt] += a01 + a11;
            }
            rlo += __shfl_xor_sync(0xffffffffu, rlo, 1);
            rlo += __shfl_xor_sync(0xffffffffu, rlo, 2);
            rhi += __shfl_xor_sync(0xffffffffu, rhi, 1);
            rhi += __shfl_xor_sync(0xffffffffu, rhi, 2);
            if (tig == 0) {
                rowbuf[wn*SS + row]   = rlo;
                rowbuf[wn*SS + row+8] = rhi;
            }
        }
#pragma unroll
        for (int nt = 0; nt < 4; nt++) {
            float c0 = cs0[nt], c1 = cs1[nt];
            c0 += __shfl_xor_sync(0xffffffffu, c0, 4);
            c0 += __shfl_xor_sync(0xffffffffu, c0, 8);
            c0 += __shfl_xor_sync(0xffffffffu, c0, 16);
            c1 += __shfl_xor_sync(0xffffffffu, c1, 4);
            c1 += __shfl_xor_sync(0xffffffffu, c1, 8);
            c1 += __shfl_xor_sync(0xffffffffu, c1, 16);
            if (g == 0) {
                int col = wn*32 + nt*8 + 2*tig;
                colbuf[wm*SS + col]     = c0;
                colbuf[wm*SS + col + 1] = c1;
            }
        }
        __syncthreads();
        if (tid < SS) {
            g_w1[b*SS + tid] = rowbuf[tid] + rowbuf[SS+tid] + rowbuf[2*SS+tid] + rowbuf[3*SS+tid];
            g_w2[b*SS + tid] = colbuf[tid] + colbuf[SS+tid];
        }
    }
#undef FETCH
#undef STBUF
}

// ---------------- f1 = A@W, f2 = A^T@W in ONE CTA, tensor cores ----------------
// grid (B, 5); 8 warps: warps 0-3 -> f1, warps 4-7 -> f2
#define FPAD 132
__global__ __launch_bounds__(256) void k_fgemm(const float* __restrict__ W, int layer) {
    extern __shared__ float sm[];
    uint32_t* As = (uint32_t*)sm;              // [128][132]
    uint32_t* Ws = As + SS*FPAD;               // [64][132] (transposed: Ws[n][k])

    int b = blockIdx.x;
    int n0 = blockIdx.y * 64;
    const float* Ab = g_A + b*SS*SS;
    const float* Wl = W + (size_t)layer*SS*EE;
    int tid = threadIdx.x;
    int lane = tid & 31, wid = tid >> 5;
    int g = lane >> 2, tig = lane & 3;
    int half = wid >> 2, wm = wid & 3;

    // load A (128x128) -> tf32 smem
    {
        int r = tid >> 1, h = tid & 1;
        const float* src = Ab + r*SS + h*64;
        uint32_t* dst = As + r*FPAD + h*64;
#pragma unroll
        for (int q = 0; q < 16; q++) {
            float4 v = *(const float4*)(src + 4*q);
            dst[4*q+0] = to_tf32(v.x); dst[4*q+1] = to_tf32(v.y);
            dst[4*q+2] = to_tf32(v.z); dst[4*q+3] = to_tf32(v.w);
        }
    }
    // load W tile transposed: Ws[n][k]
    {
        int k = tid >> 1, h = tid & 1;
#pragma unroll
        for (int q = 0; q < 8; q++) {
            int n = h*32 + 4*q;
            float4 v = make_float4(0.f,0.f,0.f,0.f);
            if (n0 + n < EE) v = *(const float4*)(Wl + k*EE + n0 + n);
            Ws[(n+0)*FPAD + k] = to_tf32(v.x);
            Ws[(n+1)*FPAD + k] = to_tf32(v.y);
            Ws[(n+2)*FPAD + k] = to_tf32(v.z);
            Ws[(n+3)*FPAD + k] = to_tf32(v.w);
        }
    }
    __syncthreads();

    float acc[2][8][4];
#pragma unroll
    for (int mt = 0; mt < 2; mt++)
#pragma unroll
        for (int nt = 0; nt < 8; nt++)
#pragma unroll
            for (int q = 0; q < 4; q++) acc[mt][nt][q] = 0.f;

#pragma unroll 4
    for (int ks = 0; ks < 16; ks++) {
        int kk = ks*8;
        uint32_t a[2][4], bf[8][2];
#pragma unroll
        for (int mt = 0; mt < 2; mt++) {
            int row = wm*32 + mt*16 + g;
            if (half == 0) {
                a[mt][0] = As[row*FPAD + kk + tig];
                a[mt][1] = As[(row+8)*FPAD + kk + tig];
                a[mt][2] = As[row*FPAD + kk + tig + 4];
                a[mt][3] = As[(row+8)*FPAD + kk + tig + 4];
            } else {
                a[mt][0] = As[(kk+tig)*FPAD + row];
                a[mt][1] = As[(kk+tig)*FPAD + row + 8];
                a[mt][2] = As[(kk+tig+4)*FPAD + row];
                a[mt][3] = As[(kk+tig+4)*FPAD + row + 8];
            }
        }
#pragma unroll
        for (int nt = 0; nt < 8; nt++) {
            int cn = nt*8 + g;
            bf[nt][0] = Ws[cn*FPAD + kk + tig];
            bf[nt][1] = Ws[cn*FPAD + kk + tig + 4];
        }
#pragma unroll
        for (int mt = 0; mt < 2; mt++)
#pragma unroll
            for (int nt = 0; nt < 8; nt++)
                MMA_TF32(acc[mt][nt], a[mt], bf[nt]);
    }

    float* out = (half ? g_f2 : g_f1) + b*SS*EE;
#pragma unroll
    for (int mt = 0; mt < 2; mt++) {
        int row = wm*32 + mt*16 + g;
#pragma unroll
        for (int nt = 0; nt < 8; nt++) {
            int col = n0 + nt*8 + 2*tig;
            if (col < EE) {
                *(float2*)(out + row*EE + col)     = make_float2(acc[mt][nt][0], acc[mt][nt][1]);
                *(float2*)(out + (row+8)*EE + col) = make_float2(acc[mt][nt][2], acc[mt][nt][3]);
            }
        }
    }
}

// ---------------- conv 2in->1out 3x3 + tanh + fused mean accumulation ----------
// grid (B, 8, 2), block 256; dynamic smem; store=0 skips global o write (dead)
__global__ __launch_bounds__(256) void k_conv(const float* __restrict__ cw,
                                              const float* __restrict__ cb,
                                              int layer, int store) {
    extern __shared__ float sm[];
    float* xs = sm;                       // [2][18][302]
    float* os = xs + 2*(CROWS+2)*(EE+2);  // [16][300]
    float* w  = os + CROWS*EE;            // [18]

    int b = blockIdx.x, ch = blockIdx.y, pair = blockIdx.z;
    int s0 = ch * CROWS;
    const float* X0 = (pair ? g_s2 : g_s1) + b*SS*EE;
    const float* X1 = (pair ? g_f2 : g_f1) + b*SS*EE;
    float* O = (pair ? g_o2 : g_o1) + b*SS*EE;
    int tid = threadIdx.x;
    if (tid < 18) w[tid] = cw[layer*18 + tid];
    if (tid < 2*(CROWS+2)*2) {
        int c = tid / (2*(CROWS+2));
        int rem = tid % (2*(CROWS+2));
        int j = rem >> 1, side = rem & 1;
        xs[(c*(CROWS+2) + j)*(EE+2) + (side ? EE+1 : 0)] = 0.f;
    }
    for (int i = tid; i < 2*(CROWS+2)*(EE/4); i += 256) {
        int c = i / ((CROWS+2)*(EE/4));
        int rem = i % ((CROWS+2)*(EE/4));
        int j = rem / (EE/4), q = rem % (EE/4);
        int srow = s0 + j - 1;
        float4 val = make_float4(0.f,0.f,0.f,0.f);
        if (srow >= 0 && srow < SS)
            val = *(const float4*)((c ? X1 : X0) + srow*EE + q*4);
        float* dptr = &xs[(c*(CROWS+2) + j)*(EE+2) + q*4 + 1];
        dptr[0]=val.x; dptr[1]=val.y; dptr[2]=val.z; dptr[3]=val.w;
    }
    float bias = cb[layer];
    __syncthreads();
    for (int i = tid; i < CROWS*EE; i += 256) {
        int r = i / EE, e = i % EE;
        float acc = bias;
#pragma unroll
        for (int c = 0; c < 2; c++)
#pragma unroll
            for (int kh = 0; kh < 3; kh++)
#pragma unroll
                for (int kw = 0; kw < 3; kw++)
                    acc += w[c*9 + kh*3 + kw] * xs[(c*(CROWS+2) + r+kh)*(EE+2) + e + kw];
        float t = tanh_fast(acc);
        if (store) O[(s0+r)*EE + e] = t;
        os[r*EE + e] = t;
    }
    __syncthreads();
    int slot = (pair ? 4 : 1) + layer;
    for (int e = tid; e < EE; e += 256) {
        float s = 0.f;
#pragma unroll
        for (int r = 0; r < CROWS; r++) s += os[r*EE + e];
        atomicAdd(&g_x[b*FCIN + slot*EE + e], s*(1.f/SS));
    }
}

// ---------------- weighted avg-pool3 + residual update ----------------
__global__ __launch_bounds__(128) void k_pool() {
    int b = blockIdx.x, ch = blockIdx.y, pair = blockIdx.z;
    int s0 = ch * CROWS;
    const float* O = (pair ? g_o2 : g_o1) + b*SS*EE;
    float* Sx = (pair ? g_s2 : g_s1) + b*SS*EE;
    const float* wv = (pair ? g_w2 : g_w1) + b*SS;
    __shared__ float w[CROWS+2];
    if (threadIdx.x < CROWS+2) {
        int s = s0 + (int)threadIdx.x - 1;
        w[threadIdx.x] = (s >= 0 && s < SS) ? wv[s] : 0.f;
    }
    __syncthreads();
    for (int e = threadIdx.x; e < EE; e += 128) {
        float a = (s0 > 0) ? O[(s0-1)*EE + e] * w[0] : 0.f;
        float bmid = O[s0*EE + e] * w[1];
#pragma unroll
        for (int i = 0; i < CROWS; i++) {
            int s = s0 + i;
            float cnext = (s+1 < SS) ? O[(s+1)*EE + e] * w[i+2] : 0.f;
            Sx[s*EE + e] += (a + bmid + cnext) * (1.f/3.f);
            a = bmid; bmid = cnext;
        }
    }
}

// ---------------- fc1 GEMM: [512,1800] @ [1800,300]^T -> g_h ----------------
__global__ __launch_bounds__(256) void k_fc1(const float* __restrict__ fw) {
    int m0 = blockIdx.x * 64, n0 = blockIdx.y * 64;
    __shared__ float Xs[8][68];
    __shared__ float Ws2[8][68];
    int tid = threadIdx.x, ty = tid >> 4, tx = tid & 15;
    float acc[4][4];
#pragma unroll
    for (int u = 0; u < 4; u++)
#pragma unroll
        for (int v = 0; v < 4; v++) acc[u][v] = 0.f;

    for (int k0 = 0; k0 < FCIN; k0 += 8) {
        __syncthreads();
#pragma unroll 2
        for (int i = tid; i < 512; i += 256) {
            int r = i >> 3, kk = i & 7;
            Xs[kk][r] = g_x[(m0 + r)*FCIN + k0 + kk];
            int n = n0 + r;
            Ws2[kk][r] = (n < HH) ? fw[n*FCIN + k0 + kk] : 0.f;
        }
        __syncthreads();
#pragma unroll
        for (int kk = 0; kk < 8; kk++) {
            float4 xa = *(const float4*)&Xs[kk][ty*4];
            float4 wb = *(const float4*)&Ws2[kk][tx*4];
            float xv[4] = {xa.x, xa.y, xa.z, xa.w};
            float wvv[4] = {wb.x, wb.y, wb.z, wb.w};
#pragma unroll
            for (int u = 0; u < 4; u++)
#pragma unroll
                for (int v = 0; v < 4; v++) acc[u][v] += xv[u]*wvv[v];
        }
    }
#pragma unroll
    for (int u = 0; u < 4; u++) {
        int m = m0 + ty*4 + u;
#pragma unroll
        for (int v = 0; v < 4; v++) {
            int n = n0 + tx*4 + v;
            if (n < HH) g_h[m*HH + n] = acc[u][v];
        }
    }
}

// ---------------- LN + relu + fc2 + softmax ----------------
__device__ __forceinline__ float block_reduce512(float v, float* red) {
    int tid = threadIdx.x;
    red[tid] = v;
    __syncthreads();
    for (int off = 256; off > 0; off >>= 1) {
        if (tid < off) red[tid] += red[tid + off];
        __syncthreads();
    }
    float r = red[0];
    __syncthreads();
    return r;
}

__global__ __launch_bounds__(512) void k_head(const float* __restrict__ fc1b,
                                              const float* __restrict__ lng,
                                              const float* __restrict__ lnb,
                                              const float* __restrict__ fc2w,
                                              const float* __restrict__ fc2b,
                                              float* __restrict__ out) {
    int b = blockIdx.x, tid = threadIdx.x;
    __shared__ float red[512];
    bool act = tid < HH;
    float h = act ? (g_h[b*HH + tid] + fc1b[tid]) : 0.f;
    float mu = block_reduce512(h, red) * (1.f/HH);
    float d = act ? (h - mu) : 0.f;
    float var = block_reduce512(d*d, red) * (1.f/HH);
    float hn = 0.f;
    if (act) {
        hn = d * rsqrtf(var + 1e-5f) * lng[tid] + lnb[tid];
        hn = fmaxf(hn, 0.f);
    }
    float o0 = block_reduce512(act ? hn*fc2w[tid]      : 0.f, red);
    float o1 = block_reduce512(act ? hn*fc2w[HH + tid] : 0.f, red);
    if (tid == 0) {
        o0 += fc2b[0];
        o1 += fc2b[1];
        out[b*2 + 0] = o0;
        out[b*2 + 1] = o1;
        float m = fmaxf(o0, o1);
        float e0 = expf(o0 - m), e1 = expf(o1 - m);
        float inv = 1.f/(e0 + e1);
        out[BB*2 + b*2 + 0] = e0*inv;
        out[BB*2 + b*2 + 1] = e1*inv;
    }
}

// ---------------- launch ----------------
extern "C" void kernel_launch(void* const* d_in, const int* in_sizes, int n_in,
                              void* d_out, int out_size) {
    (void)in_sizes; (void)n_in; (void)out_size;
    const int*   seq1 = (const int*)d_in[0];
    const int*   seq2 = (const int*)d_in[1];
    const float* emb  = (const float*)d_in[2];
    const float* W    = (const float*)d_in[3];
    const float* cw   = (const float*)d_in[4];
    const float* cb   = (const float*)d_in[5];
    const float* fc1w = (const float*)d_in[6];
    const float* fc1b = (const float*)d_in[7];
    const float* lng  = (const float*)d_in[8];
    const float* lnb  = (const float*)d_in[9];
    const float* fc2w = (const float*)d_in[10];
    const float* fc2b = (const float*)d_in[11];
    float* out = (float*)d_out;

    const int SM_MATCH = (2*SS*MPAD*2 + 2*SS + 4*SS + 2*SS) * 4;    // ~77.8KB
    const int SM_FGEMM = (SS*FPAD + 64*FPAD) * 4;                    // ~101.4KB
    const int SM_CONV  = (2*(CROWS+2)*(EE+2) + CROWS*EE + 18) * 4;   // ~62.8KB

    cudaFuncSetAttribute(k_match, cudaFuncAttributeMaxDynamicSharedMemorySize, SM_MATCH);
    cudaFuncSetAttribute(k_fgemm, cudaFuncAttributeMaxDynamicSharedMemorySize, SM_FGEMM);
    cudaFuncSetAttribute(k_conv,  cudaFuncAttributeMaxDynamicSharedMemorySize, SM_CONV);

    k_gather<<<BB, 256>>>(seq1, seq2, emb);
    for (int l = 0; l < LL; l++) {
        int last = (l == LL-1);
        k_match<<<BB, 256, SM_MATCH>>>(0);
        k_zx<<<(BB*2*EE + 255)/256, 256>>>(l);
        k_fgemm<<<dim3(BB, 5), 256, SM_FGEMM>>>(W, l);
        k_conv<<<dim3(BB, 8, 2), 256, SM_CONV>>>(cw, cb, l, last ? 0 : 1);
        if (!last) {
            k_match<<<BB, 256, SM_MATCH>>>(1);
            k_pool<<<dim3(BB, 8, 2), 128>>>();
        }
    }
    k_fc1<<<dim3(8, 5), 256>>>(fc1w);
    k_head<<<BB, 512>>>(fc1b, lng, lnb, fc2w, fc2b, out);
}